// round 1
// baseline (speedup 1.0000x reference)
#include <cuda_runtime.h>

#define BATCH 4
#define CIN 256
#define CO 128
#define HIN 64
#define WIN 64
#define HOUT 128
#define WOUT 128

// Scratch (static device globals — no allocation)
__device__ float g_y[BATCH * CO * HOUT * WOUT];   // conv_transpose output (33.5 MB)
__device__ float g_k[BATCH * 9 * HOUT * WOUT];    // PAC gaussian kernel map (2.4 MB)

// ---------------------------------------------------------------------------
// Kernel 1: conv_transpose 4x4, stride 2, pad 1.
// y[b,co,2m+r,2n+s] = b1[co] + sum_ci sum_{dr,ds} x[b,ci,ih(dr),iw(ds)] * w1[ci,co,kh(dr),kw(ds)]
//   r=0: dr0->(ih=m,  kh=1), dr1->(ih=m-1,kh=3)
//   r=1: dr0->(ih=m,  kh=2), dr1->(ih=m+1,kh=0)   (cols identical with s)
// Tile: 64 co x (4m x 32n) pixels of one parity class. 256 threads, 8x4 microtile.
// ---------------------------------------------------------------------------
#define K1_COT 64
#define K1_MT 4
#define K1_NT 32
#define K1_CK 8

__global__ __launch_bounds__(256) void convt_kernel(const float* __restrict__ x,
                                                    const float* __restrict__ w1,
                                                    const float* __restrict__ b1) {
    const int bz = blockIdx.z;
    const int b = bz >> 2;
    const int cls = bz & 3;
    const int r = cls >> 1, s = cls & 1;
    const int co0 = (blockIdx.y >> 4) * K1_COT;
    const int m0 = (blockIdx.y & 15) * K1_MT;
    const int n0 = blockIdx.x * K1_NT;

    __shared__ float sx[K1_CK][6][K1_NT + 2];
    __shared__ float sw[4][K1_CK][K1_COT];

    const int t = threadIdx.x;
    const int tp = t & 31;   // pixel column lane
    const int tc = t >> 5;   // co group (warp-uniform)

    float acc[8][4];
#pragma unroll
    for (int u = 0; u < 8; u++)
#pragma unroll
        for (int q = 0; q < 4; q++) acc[u][q] = 0.f;

    // smem row index for pixel-row q, tap dr:  q + rowadd[dr]  (rows loaded from m0-1)
    const int rowadd[2] = {1, r ? 2 : 0};
    const int coladd[2] = {1, s ? 2 : 0};
    const int khs[2] = {r ? 2 : 1, r ? 0 : 3};
    const int kws[2] = {s ? 2 : 1, s ? 0 : 3};

    for (int cb = 0; cb < CIN; cb += K1_CK) {
        // load x halo tile: CK x 6 x 34
        for (int e = t; e < K1_CK * 6 * (K1_NT + 2); e += 256) {
            int ci = e / (6 * (K1_NT + 2));
            int rem = e - ci * 6 * (K1_NT + 2);
            int row = rem / (K1_NT + 2);
            int col = rem - row * (K1_NT + 2);
            int ih = m0 - 1 + row;
            int iw = n0 - 1 + col;
            float v = 0.f;
            if (ih >= 0 && ih < HIN && iw >= 0 && iw < WIN)
                v = x[((b * CIN + cb + ci) * HIN + ih) * WIN + iw];
            sx[ci][row][col] = v;
        }
        // load weights for the 4 taps of this class: 4 x CK x 64
        for (int e = t; e < 4 * K1_CK * K1_COT; e += 256) {
            int tap = e / (K1_CK * K1_COT);
            int rem = e - tap * (K1_CK * K1_COT);
            int ci = rem / K1_COT;
            int col = rem - ci * K1_COT;
            int dr = tap >> 1, ds = tap & 1;
            sw[tap][ci][col] =
                w1[(((cb + ci) * CO + co0 + col) << 4) + (khs[dr] << 2) + kws[ds]];
        }
        __syncthreads();

#pragma unroll
        for (int ci = 0; ci < K1_CK; ci++) {
#pragma unroll
            for (int tap = 0; tap < 4; tap++) {
                const int dr = tap >> 1, ds = tap & 1;
                float wv[8];
#pragma unroll
                for (int u = 0; u < 8; u++) wv[u] = sw[tap][ci][tc * 8 + u];
                float xv[4];
#pragma unroll
                for (int q = 0; q < 4; q++)
                    xv[q] = sx[ci][q + rowadd[dr]][tp + coladd[ds]];
#pragma unroll
                for (int u = 0; u < 8; u++)
#pragma unroll
                    for (int q = 0; q < 4; q++) acc[u][q] += wv[u] * xv[q];
            }
        }
        __syncthreads();
    }

#pragma unroll
    for (int u = 0; u < 8; u++) {
        int co = co0 + tc * 8 + u;
        float bias = __ldg(&b1[co]);
#pragma unroll
        for (int q = 0; q < 4; q++) {
            int oh = 2 * (m0 + q) + r;
            int ow = 2 * (n0 + tp) + s;
            g_y[((b * CO + co) * HOUT + oh) * WOUT + ow] = acc[u][q] + bias;
        }
    }
}

// ---------------------------------------------------------------------------
// Kernel 2: guide kernel map.
// k[b,tap,h,w] = exp(-0.5 * sum_c (G[c, h+di-1, w+dj-1] - G[c,h,w])^2), OOB guide = 0.
// 16x16 pixel tile, 1 pixel/thread, 9 accumulators, channel-chunked smem.
// ---------------------------------------------------------------------------
#define K2_CK 8

__global__ __launch_bounds__(256) void kmap_kernel(const float* __restrict__ guide) {
    const int b = blockIdx.z;
    const int h0 = blockIdx.y * 16;
    const int w0 = blockIdx.x * 16;
    __shared__ float sg[K2_CK][18][18];
    const int t = threadIdx.x;
    const int tx = t & 15, ty = t >> 4;

    float acc[9];
#pragma unroll
    for (int i = 0; i < 9; i++) acc[i] = 0.f;

    for (int cb = 0; cb < CO; cb += K2_CK) {
        for (int e = t; e < K2_CK * 18 * 18; e += 256) {
            int c = e / 324;
            int rem = e - c * 324;
            int row = rem / 18, col = rem - row * 18;
            int gh = h0 - 1 + row, gw = w0 - 1 + col;
            float v = 0.f;
            if (gh >= 0 && gh < HOUT && gw >= 0 && gw < WOUT)
                v = guide[((b * CO + cb + c) * HOUT + gh) * WOUT + gw];
            sg[c][row][col] = v;
        }
        __syncthreads();
#pragma unroll
        for (int c = 0; c < K2_CK; c++) {
            float gc = sg[c][ty + 1][tx + 1];
#pragma unroll
            for (int tap = 0; tap < 9; tap++) {
                int di = tap / 3, dj = tap % 3;
                float d = sg[c][ty + di][tx + dj] - gc;
                acc[tap] += d * d;
            }
        }
        __syncthreads();
    }
#pragma unroll
    for (int tap = 0; tap < 9; tap++)
        g_k[((b * 9 + tap) * HOUT + h0 + ty) * WOUT + w0 + tx] = __expf(-0.5f * acc[tap]);
}

// ---------------------------------------------------------------------------
// Kernel 3: PAC conv (k-modulated 9-tap GEMM).
// out[b,o,h,w] = b2[o] + sum_tap k[b,tap,h,w] * sum_c w2[c,o,2-i,2-j] * y[b,c,h+i-1,w+j-1]
// Tile: 64 co x (4h x 32w), 256 threads, 8x4 microtile, tap-outer/ci-inner loop.
// ---------------------------------------------------------------------------
#define K3_COT 64
#define K3_HT 4
#define K3_WT 32
#define K3_CK 8

__global__ __launch_bounds__(256) void pac_kernel(const float* __restrict__ w2,
                                                  const float* __restrict__ b2,
                                                  float* __restrict__ out) {
    const int bz = blockIdx.z;  // b*2 + co_tile
    const int b = bz >> 1;
    const int co0 = (bz & 1) * K3_COT;
    const int h0 = blockIdx.y * K3_HT;
    const int w0 = blockIdx.x * K3_WT;

    __shared__ float sy[K3_CK][6][K3_WT + 2];
    __shared__ float sw[9][K3_CK][K3_COT];
    __shared__ float sk[9][K3_HT][K3_WT];

    const int t = threadIdx.x;
    const int tp = t & 31, tc = t >> 5;

    // load k tile once
    for (int e = t; e < 9 * K3_HT * K3_WT; e += 256) {
        int tap = e / (K3_HT * K3_WT);
        int rem = e - tap * (K3_HT * K3_WT);
        int row = rem >> 5;
        int col = rem & 31;
        sk[tap][row][col] = g_k[((b * 9 + tap) * HOUT + h0 + row) * WOUT + w0 + col];
    }

    float acc[8][4];
#pragma unroll
    for (int u = 0; u < 8; u++)
#pragma unroll
        for (int q = 0; q < 4; q++) acc[u][q] = 0.f;

    for (int cb = 0; cb < CO; cb += K3_CK) {
        // y halo tile: CK x 6 x 34
        for (int e = t; e < K3_CK * 6 * (K3_WT + 2); e += 256) {
            int ci = e / 204;
            int rem = e - ci * 204;
            int row = rem / 34, col = rem - row * 34;
            int yh = h0 - 1 + row, yw = w0 - 1 + col;
            float v = 0.f;
            if (yh >= 0 && yh < HOUT && yw >= 0 && yw < WOUT)
                v = g_y[((b * CO + cb + ci) * HOUT + yh) * WOUT + yw];
            sy[ci][row][col] = v;
        }
        // flipped+transposed w2: 9 x CK x 64
        for (int e = t; e < 9 * K3_CK * K3_COT; e += 256) {
            int tap = e / (K3_CK * K3_COT);
            int rem = e - tap * (K3_CK * K3_COT);
            int ci = rem / K3_COT;
            int col = rem - ci * K3_COT;
            int i = tap / 3, j = tap % 3;
            sw[tap][ci][col] = w2[((cb + ci) * CO + co0 + col) * 9 + (2 - i) * 3 + (2 - j)];
        }
        __syncthreads();

#pragma unroll
        for (int tap = 0; tap < 9; tap++) {
            const int di = tap / 3, dj = tap % 3;
            float kq[4];
#pragma unroll
            for (int q = 0; q < 4; q++) kq[q] = sk[tap][q][tp];
#pragma unroll
            for (int ci = 0; ci < K3_CK; ci++) {
                float wv[8];
#pragma unroll
                for (int u = 0; u < 8; u++) wv[u] = sw[tap][ci][tc * 8 + u];
                float xv[4];
#pragma unroll
                for (int q = 0; q < 4; q++)
                    xv[q] = sy[ci][q + di][tp + dj] * kq[q];
#pragma unroll
                for (int u = 0; u < 8; u++)
#pragma unroll
                    for (int q = 0; q < 4; q++) acc[u][q] += wv[u] * xv[q];
            }
        }
        __syncthreads();
    }

#pragma unroll
    for (int u = 0; u < 8; u++) {
        int co = co0 + tc * 8 + u;
        float bias = __ldg(&b2[co]);
#pragma unroll
        for (int q = 0; q < 4; q++)
            out[((b * CO + co) * HOUT + h0 + q) * WOUT + w0 + tp] = acc[u][q] + bias;
    }
}

// ---------------------------------------------------------------------------
// Launch. Inputs (metadata order): x, guide, w1, b1, w2, b2. Output: float32.
// ---------------------------------------------------------------------------
extern "C" void kernel_launch(void* const* d_in, const int* in_sizes, int n_in,
                              void* d_out, int out_size) {
    const float* x = (const float*)d_in[0];
    const float* guide = (const float*)d_in[1];
    const float* w1 = (const float*)d_in[2];
    const float* b1 = (const float*)d_in[3];
    const float* w2 = (const float*)d_in[4];
    const float* b2 = (const float*)d_in[5];
    float* out = (float*)d_out;

    // conv_transpose: grid (n_tiles=2, co_tiles*m_tiles=2*16, B*4 classes)
    convt_kernel<<<dim3(2, 32, 16), 256>>>(x, w1, b1);
    // guide kernel map: grid (8, 8, B)
    kmap_kernel<<<dim3(8, 8, 4), 256>>>(guide);
    // PAC conv: grid (w_tiles=4, h_tiles=32, B*co_tiles=8)
    pac_kernel<<<dim3(4, 32, 8), 256>>>(w2, b2, out);
}

// round 2
// speedup vs baseline: 1.2669x; 1.2669x over previous
#include <cuda_runtime.h>

#define BATCH 4
#define CIN 256
#define CO 128
#define HIN 64
#define WIN 64
#define HOUT 128
#define WOUT 128

// Scratch (static device globals — no allocation)
__device__ float g_y[BATCH * CO * HOUT * WOUT];   // conv_transpose output
__device__ float g_k[BATCH * 9 * HOUT * WOUT];    // PAC gaussian kernel map
__device__ float g_w1t[16 * CIN * CO];            // w1 transposed [k][ci][co]
__device__ float g_w2t[9 * CO * CO];              // w2 flipped+transposed [tap][ci][co]

typedef unsigned long long u64;

__device__ __forceinline__ void ffma2(u64 &d, u64 a, u64 b) {
    asm("fma.rn.f32x2 %0, %1, %2, %0;" : "+l"(d) : "l"(a), "l"(b));
}
__device__ __forceinline__ u64 dup2(float x) {
    u64 r; asm("mov.b64 %0, {%1, %1};" : "=l"(r) : "f"(x)); return r;
}
__device__ __forceinline__ float2 unpack2(u64 v) {
    float2 f; asm("mov.b64 {%0, %1}, %2;" : "=f"(f.x), "=f"(f.y) : "l"(v)); return f;
}

// ---------------------------------------------------------------------------
// One-shot weight transposes (coalesced writes).
// g_w1t[k][ci][co] = w1[(ci*CO+co)*16 + k]
// g_w2t[tap][ci][co] = w2[(ci*CO+co)*9 + 8 - tap]   (pre-flipped for PAC)
// ---------------------------------------------------------------------------
__global__ __launch_bounds__(256) void tw1_kernel(const float* __restrict__ w1) {
    int g = blockIdx.x * 256 + threadIdx.x;           // 16*256*128 = 524288
    int k = g >> 15;
    int ci = (g >> 7) & 255;
    int co = g & 127;
    g_w1t[g] = w1[((ci << 7) + co) * 16 + k];
}
__global__ __launch_bounds__(256) void tw2_kernel(const float* __restrict__ w2) {
    int g = blockIdx.x * 256 + threadIdx.x;           // 9*128*128 = 147456
    int tap = g >> 14;
    int ci = (g >> 7) & 127;
    int co = g & 127;
    g_w2t[g] = w2[((ci << 7) + co) * 9 + 8 - tap];
}

// ---------------------------------------------------------------------------
// Kernel 1: conv_transpose 4x4 s2 p1, parity-decomposed (4 taps per class).
// 64 co x (4m x 32n) tile, 256 thr, co-pair-packed FFMA2 microtile 4x4(pairs).
// ---------------------------------------------------------------------------
#define K1_CK 16

__global__ __launch_bounds__(256) void convt_kernel(const float* __restrict__ x,
                                                    const float* __restrict__ b1) {
    const int bz = blockIdx.z;
    const int b = bz >> 2;
    const int cls = bz & 3;
    const int r = cls >> 1, s = cls & 1;
    const int co0 = (blockIdx.y >> 4) * 64;
    const int m0 = (blockIdx.y & 15) * 4;
    const int n0 = blockIdx.x * 32;

    __shared__ float sx[K1_CK * 6 * 34];
    __shared__ float sw[4][K1_CK][64];

    const int t = threadIdx.x;
    const int tp = t & 31;
    const int tc = t >> 5;

    const int rowadd[2] = {1, r ? 2 : 0};
    const int coladd[2] = {1, s ? 2 : 0};
    const int khs[2] = {r ? 2 : 1, r ? 0 : 3};
    const int kws[2] = {s ? 2 : 1, s ? 0 : 3};
    int xoff[4], kidx[4];
#pragma unroll
    for (int tap = 0; tap < 4; tap++) {
        xoff[tap] = rowadd[tap >> 1] * 34 + coladd[tap & 1] + tp;
        kidx[tap] = khs[tap >> 1] * 4 + kws[tap & 1];
    }

    u64 acc[4][4];
#pragma unroll
    for (int p = 0; p < 4; p++)
#pragma unroll
        for (int q = 0; q < 4; q++) acc[p][q] = 0ull;

    for (int cb = 0; cb < CIN; cb += K1_CK) {
        // x halo tile: CK x 6 x 34
        for (int e = t; e < K1_CK * 6 * 34; e += 256) {
            int ci = e / 204;
            int rem = e - ci * 204;
            int row = rem / 34, col = rem - row * 34;
            int ih = m0 - 1 + row, iw = n0 - 1 + col;
            float v = 0.f;
            if ((unsigned)ih < HIN && (unsigned)iw < WIN)
                v = x[((b * CIN + cb + ci) * HIN + ih) * WIN + iw];
            sx[e] = v;
        }
        // weights: 4 taps x CK x 64, coalesced float4 from g_w1t
        for (int e = t; e < 4 * K1_CK * 16; e += 256) {
            int tap = e >> 8;
            int rem = e & 255;
            int ci = rem >> 4;
            int c4 = (rem & 15) << 2;
            *(float4*)&sw[tap][ci][c4] =
                *(const float4*)&g_w1t[(kidx[tap] * CIN + cb + ci) * CO + co0 + c4];
        }
        __syncthreads();

#pragma unroll 4
        for (int ci = 0; ci < K1_CK; ci++) {
#pragma unroll
            for (int tap = 0; tap < 4; tap++) {
                u64 w0 = *(const u64*)&sw[tap][ci][tc * 8 + 0];
                u64 w1v = *(const u64*)&sw[tap][ci][tc * 8 + 2];
                u64 w2v = *(const u64*)&sw[tap][ci][tc * 8 + 4];
                u64 w3v = *(const u64*)&sw[tap][ci][tc * 8 + 6];
                const float* sp = &sx[ci * 204 + xoff[tap]];
                u64 x0 = dup2(sp[0]);
                u64 x1 = dup2(sp[34]);
                u64 x2 = dup2(sp[68]);
                u64 x3 = dup2(sp[102]);
                ffma2(acc[0][0], w0, x0); ffma2(acc[1][0], w1v, x0);
                ffma2(acc[2][0], w2v, x0); ffma2(acc[3][0], w3v, x0);
                ffma2(acc[0][1], w0, x1); ffma2(acc[1][1], w1v, x1);
                ffma2(acc[2][1], w2v, x1); ffma2(acc[3][1], w3v, x1);
                ffma2(acc[0][2], w0, x2); ffma2(acc[1][2], w1v, x2);
                ffma2(acc[2][2], w2v, x2); ffma2(acc[3][2], w3v, x2);
                ffma2(acc[0][3], w0, x3); ffma2(acc[1][3], w1v, x3);
                ffma2(acc[2][3], w2v, x3); ffma2(acc[3][3], w3v, x3);
            }
        }
        __syncthreads();
    }

#pragma unroll
    for (int p = 0; p < 4; p++) {
        int co = co0 + tc * 8 + 2 * p;
        float2 bias = *(const float2*)&b1[co];
#pragma unroll
        for (int q = 0; q < 4; q++) {
            float2 v = unpack2(acc[p][q]);
            int oh = 2 * (m0 + q) + r;
            int ow = 2 * (n0 + tp) + s;
            float* dst = &g_y[((b * CO + co) * HOUT + oh) * WOUT + ow];
            dst[0] = v.x + bias.x;
            dst[HOUT * WOUT] = v.y + bias.y;
        }
    }
}

// ---------------------------------------------------------------------------
// Kernel 2: guide gaussian kernel map (unchanged from R1).
// ---------------------------------------------------------------------------
#define K2_CK 8

__global__ __launch_bounds__(256) void kmap_kernel(const float* __restrict__ guide) {
    const int b = blockIdx.z;
    const int h0 = blockIdx.y * 16;
    const int w0 = blockIdx.x * 16;
    __shared__ float sg[K2_CK][18][18];
    const int t = threadIdx.x;
    const int tx = t & 15, ty = t >> 4;

    float acc[9];
#pragma unroll
    for (int i = 0; i < 9; i++) acc[i] = 0.f;

    for (int cb = 0; cb < CO; cb += K2_CK) {
        for (int e = t; e < K2_CK * 18 * 18; e += 256) {
            int c = e / 324;
            int rem = e - c * 324;
            int row = rem / 18, col = rem - row * 18;
            int gh = h0 - 1 + row, gw = w0 - 1 + col;
            float v = 0.f;
            if ((unsigned)gh < HOUT && (unsigned)gw < WOUT)
                v = guide[((b * CO + cb + c) * HOUT + gh) * WOUT + gw];
            sg[c][row][col] = v;
        }
        __syncthreads();
#pragma unroll
        for (int c = 0; c < K2_CK; c++) {
            float gc = sg[c][ty + 1][tx + 1];
#pragma unroll
            for (int tap = 0; tap < 9; tap++) {
                int di = tap / 3, dj = tap % 3;
                float d = sg[c][ty + di][tx + dj] - gc;
                acc[tap] += d * d;
            }
        }
        __syncthreads();
    }
#pragma unroll
    for (int tap = 0; tap < 9; tap++)
        g_k[((b * 9 + tap) * HOUT + h0 + ty) * WOUT + w0 + tx] = __expf(-0.5f * acc[tap]);
}

// ---------------------------------------------------------------------------
// Kernel 3: PAC conv — k-modulated 9-tap GEMM with FFMA2 co-pair packing.
// ---------------------------------------------------------------------------
#define K3_CK 8

__global__ __launch_bounds__(256) void pac_kernel(const float* __restrict__ b2,
                                                  float* __restrict__ out) {
    const int bz = blockIdx.z;  // b*2 + co_tile
    const int b = bz >> 1;
    const int co0 = (bz & 1) * 64;
    const int h0 = blockIdx.y * 4;
    const int w0 = blockIdx.x * 32;

    __shared__ float sy[K3_CK * 6 * 34];
    __shared__ float sw[9][K3_CK][64];
    __shared__ float sk[9][4][32];

    const int t = threadIdx.x;
    const int tp = t & 31, tc = t >> 5;

    // k tile once
    for (int e = t; e < 9 * 4 * 32; e += 256) {
        int tap = e >> 7;
        int rem = e & 127;
        sk[tap][rem >> 5][rem & 31] =
            g_k[((b * 9 + tap) * HOUT + h0 + (rem >> 5)) * WOUT + w0 + (rem & 31)];
    }

    u64 acc[4][4];
#pragma unroll
    for (int p = 0; p < 4; p++)
#pragma unroll
        for (int q = 0; q < 4; q++) acc[p][q] = 0ull;

    for (int cb = 0; cb < CO; cb += K3_CK) {
        // y halo tile: CK x 6 x 34
        for (int e = t; e < K3_CK * 6 * 34; e += 256) {
            int ci = e / 204;
            int rem = e - ci * 204;
            int row = rem / 34, col = rem - row * 34;
            int yh = h0 - 1 + row, yw = w0 - 1 + col;
            float v = 0.f;
            if ((unsigned)yh < HOUT && (unsigned)yw < WOUT)
                v = g_y[((b * CO + cb + ci) * HOUT + yh) * WOUT + yw];
            sy[e] = v;
        }
        // weights: 9 taps x CK x 64, coalesced float4 from g_w2t (pre-flipped)
        for (int e = t; e < 9 * K3_CK * 16; e += 256) {
            int tap = e >> 7;
            int rem = e & 127;
            int ci = rem >> 4;
            int c4 = (rem & 15) << 2;
            *(float4*)&sw[tap][ci][c4] =
                *(const float4*)&g_w2t[(tap * CO + cb + ci) * CO + co0 + c4];
        }
        __syncthreads();

#pragma unroll
        for (int tap = 0; tap < 9; tap++) {
            const int di = tap / 3, dj = tap - 3 * (tap / 3);
            float k0 = sk[tap][0][tp];
            float k1 = sk[tap][1][tp];
            float k2 = sk[tap][2][tp];
            float k3 = sk[tap][3][tp];
            const float* syb = &sy[di * 34 + dj + tp];
#pragma unroll 2
            for (int ci = 0; ci < K3_CK; ci++) {
                u64 w0 = *(const u64*)&sw[tap][ci][tc * 8 + 0];
                u64 w1v = *(const u64*)&sw[tap][ci][tc * 8 + 2];
                u64 w2v = *(const u64*)&sw[tap][ci][tc * 8 + 4];
                u64 w3v = *(const u64*)&sw[tap][ci][tc * 8 + 6];
                const float* sp = syb + ci * 204;
                u64 x0 = dup2(sp[0] * k0);
                u64 x1 = dup2(sp[34] * k1);
                u64 x2 = dup2(sp[68] * k2);
                u64 x3 = dup2(sp[102] * k3);
                ffma2(acc[0][0], w0, x0); ffma2(acc[1][0], w1v, x0);
                ffma2(acc[2][0], w2v, x0); ffma2(acc[3][0], w3v, x0);
                ffma2(acc[0][1], w0, x1); ffma2(acc[1][1], w1v, x1);
                ffma2(acc[2][1], w2v, x1); ffma2(acc[3][1], w3v, x1);
                ffma2(acc[0][2], w0, x2); ffma2(acc[1][2], w1v, x2);
                ffma2(acc[2][2], w2v, x2); ffma2(acc[3][2], w3v, x2);
                ffma2(acc[0][3], w0, x3); ffma2(acc[1][3], w1v, x3);
                ffma2(acc[2][3], w2v, x3); ffma2(acc[3][3], w3v, x3);
            }
        }
        __syncthreads();
    }

#pragma unroll
    for (int p = 0; p < 4; p++) {
        int co = co0 + tc * 8 + 2 * p;
        float2 bias = *(const float2*)&b2[co];
#pragma unroll
        for (int q = 0; q < 4; q++) {
            float2 v = unpack2(acc[p][q]);
            float* dst = &out[((b * CO + co) * HOUT + h0 + q) * WOUT + w0 + tp];
            dst[0] = v.x + bias.x;
            dst[HOUT * WOUT] = v.y + bias.y;
        }
    }
}

// ---------------------------------------------------------------------------
// Launch. Inputs (metadata order): x, guide, w1, b1, w2, b2. Output: float32.
// ---------------------------------------------------------------------------
extern "C" void kernel_launch(void* const* d_in, const int* in_sizes, int n_in,
                              void* d_out, int out_size) {
    const float* x = (const float*)d_in[0];
    const float* guide = (const float*)d_in[1];
    const float* w1 = (const float*)d_in[2];
    const float* b1 = (const float*)d_in[3];
    const float* w2 = (const float*)d_in[4];
    const float* b2 = (const float*)d_in[5];
    float* out = (float*)d_out;

    tw1_kernel<<<2048, 256>>>(w1);
    tw2_kernel<<<576, 256>>>(w2);
    kmap_kernel<<<dim3(8, 8, 4), 256>>>(guide);
    convt_kernel<<<dim3(2, 32, 16), 256>>>(x, b1);
    pac_kernel<<<dim3(4, 32, 8), 256>>>(b2, out);
}

// round 3
// speedup vs baseline: 1.4122x; 1.1147x over previous
#include <cuda_runtime.h>

#define BATCH 4
#define CIN 256
#define CO 128
#define HIN 64
#define WIN 64
#define HOUT 128
#define WOUT 128

__device__ float g_y[BATCH * CO * HOUT * WOUT];
__device__ float g_k[BATCH * 9 * HOUT * WOUT];
__device__ float g_w1t[16 * CIN * CO];
__device__ float g_w2t[9 * CO * CO];

typedef unsigned long long u64;

__device__ __forceinline__ void ffma2(u64 &d, u64 a, u64 b) {
    asm("fma.rn.f32x2 %0, %1, %2, %0;" : "+l"(d) : "l"(a), "l"(b));
}
__device__ __forceinline__ u64 dup2(float x) {
    u64 r; asm("mov.b64 %0, {%1, %1};" : "=l"(r) : "f"(x)); return r;
}
__device__ __forceinline__ float2 unpack2(u64 v) {
    float2 f; asm("mov.b64 {%0, %1}, %2;" : "=f"(f.x), "=f"(f.y) : "l"(v)); return f;
}
__device__ __forceinline__ void cp4(unsigned s, const void* g, int ok) {
    asm volatile("cp.async.ca.shared.global [%0], [%1], 4, %2;" :: "r"(s), "l"(g), "r"(ok * 4));
}
__device__ __forceinline__ void cp16(unsigned s, const void* g) {
    asm volatile("cp.async.cg.shared.global [%0], [%1], 16;" :: "r"(s), "l"(g));
}
#define CP_COMMIT asm volatile("cp.async.commit_group;" ::: "memory")
#define CP_WAIT0 asm volatile("cp.async.wait_group 0;" ::: "memory")

// ---------------------------------------------------------------------------
// One-shot weight transposes.
// ---------------------------------------------------------------------------
__global__ __launch_bounds__(256) void tw1_kernel(const float* __restrict__ w1) {
    int g = blockIdx.x * 256 + threadIdx.x;
    int k = g >> 15;
    int ci = (g >> 7) & 255;
    int co = g & 127;
    g_w1t[g] = w1[((ci << 7) + co) * 16 + k];
}
__global__ __launch_bounds__(256) void tw2_kernel(const float* __restrict__ w2) {
    int g = blockIdx.x * 256 + threadIdx.x;
    int tap = g >> 14;
    int ci = (g >> 7) & 127;
    int co = g & 127;
    g_w2t[g] = w2[((ci << 7) + co) * 9 + 8 - tap];
}

// ---------------------------------------------------------------------------
// Kernel 1: conv_transpose 4x4 s2 p1, parity classes, cp.async double buffer.
// ---------------------------------------------------------------------------
#define K1_CK 16
#define K1_XT (K1_CK * 6 * 34)      // 3264 floats per buffer
#define K1_WT (4 * K1_CK * 64)      // 4096 floats per buffer

__global__ __launch_bounds__(256) void convt_kernel(const float* __restrict__ x,
                                                    const float* __restrict__ b1) {
    const int bz = blockIdx.z;
    const int b = bz >> 2;
    const int cls = bz & 3;
    const int r = cls >> 1, s = cls & 1;
    const int co0 = (blockIdx.y >> 4) * 64;
    const int m0 = (blockIdx.y & 15) * 4;
    const int n0 = blockIdx.x * 32;

    __shared__ float sxs[2][K1_XT];
    __shared__ float sws[2][K1_WT];

    const int t = threadIdx.x;
    const int tp = t & 31;
    const int tc = t >> 5;

    const int rowadd[2] = {1, r ? 2 : 0};
    const int coladd[2] = {1, s ? 2 : 0};
    const int khs[2] = {r ? 2 : 1, r ? 0 : 3};
    const int kws[2] = {s ? 2 : 1, s ? 0 : 3};
    int xoff[4], kidx[4];
#pragma unroll
    for (int tap = 0; tap < 4; tap++) {
        xoff[tap] = rowadd[tap >> 1] * 34 + coladd[tap & 1] + tp;
        kidx[tap] = khs[tap >> 1] * 4 + kws[tap & 1];
    }

    u64 acc[4][4];
#pragma unroll
    for (int p = 0; p < 4; p++)
#pragma unroll
        for (int q = 0; q < 4; q++) acc[p][q] = 0ull;

    const unsigned sx_s0 = (unsigned)__cvta_generic_to_shared(&sxs[0][0]);
    const unsigned sw_s0 = (unsigned)__cvta_generic_to_shared(&sws[0][0]);

    // prefetch lambda-ish macro via explicit code
    auto prefetch = [&](int cb, int buf) {
        unsigned sx_s = sx_s0 + buf * (K1_XT * 4);
        unsigned sw_s = sw_s0 + buf * (K1_WT * 4);
#pragma unroll
        for (int it = 0; it < 13; it++) {
            int e = t + it * 256;
            if (e < K1_XT) {
                int ci = e / 204;
                int rem = e - ci * 204;
                int row = rem / 34, col = rem - row * 34;
                int ih = m0 - 1 + row, iw = n0 - 1 + col;
                int ok = ((unsigned)ih < HIN && (unsigned)iw < WIN) ? 1 : 0;
                const float* g = ok ? &x[((b * CIN + cb + ci) * HIN + ih) * WIN + iw] : x;
                cp4(sx_s + e * 4, g, ok);
            }
        }
#pragma unroll
        for (int it = 0; it < 4; it++) {
            int e = t + it * 256;          // < 1024 16B ops
            int tap = e >> 8;
            int rem = e & 255;
            int ci = rem >> 4;
            int c4 = (rem & 15) << 2;
            cp16(sw_s + (((tap * K1_CK + ci) << 6) + c4) * 4,
                 &g_w1t[(kidx[tap] * CIN + cb + ci) * CO + co0 + c4]);
        }
    };

    prefetch(0, 0);
    CP_COMMIT;

    int buf = 0;
    for (int cb = 0; cb < CIN; cb += K1_CK) {
        CP_WAIT0;
        __syncthreads();
        if (cb + K1_CK < CIN) {
            prefetch(cb + K1_CK, buf ^ 1);
            CP_COMMIT;
        }
        const float* sx = sxs[buf];
        const float* sw = sws[buf];

#pragma unroll 4
        for (int ci = 0; ci < K1_CK; ci++) {
#pragma unroll
            for (int tap = 0; tap < 4; tap++) {
                const float* wp = &sw[((tap * K1_CK + ci) << 6) + tc * 8];
                u64 w0 = *(const u64*)&wp[0];
                u64 w1v = *(const u64*)&wp[2];
                u64 w2v = *(const u64*)&wp[4];
                u64 w3v = *(const u64*)&wp[6];
                const float* sp = &sx[ci * 204 + xoff[tap]];
                u64 x0 = dup2(sp[0]);
                u64 x1 = dup2(sp[34]);
                u64 x2 = dup2(sp[68]);
                u64 x3 = dup2(sp[102]);
                ffma2(acc[0][0], w0, x0); ffma2(acc[1][0], w1v, x0);
                ffma2(acc[2][0], w2v, x0); ffma2(acc[3][0], w3v, x0);
                ffma2(acc[0][1], w0, x1); ffma2(acc[1][1], w1v, x1);
                ffma2(acc[2][1], w2v, x1); ffma2(acc[3][1], w3v, x1);
                ffma2(acc[0][2], w0, x2); ffma2(acc[1][2], w1v, x2);
                ffma2(acc[2][2], w2v, x2); ffma2(acc[3][2], w3v, x2);
                ffma2(acc[0][3], w0, x3); ffma2(acc[1][3], w1v, x3);
                ffma2(acc[2][3], w2v, x3); ffma2(acc[3][3], w3v, x3);
            }
        }
        buf ^= 1;
    }

#pragma unroll
    for (int p = 0; p < 4; p++) {
        int co = co0 + tc * 8 + 2 * p;
        float2 bias = *(const float2*)&b1[co];
#pragma unroll
        for (int q = 0; q < 4; q++) {
            float2 v = unpack2(acc[p][q]);
            int oh = 2 * (m0 + q) + r;
            int ow = 2 * (n0 + tp) + s;
            float* dst = &g_y[((b * CO + co) * HOUT + oh) * WOUT + ow];
            dst[0] = v.x + bias.x;
            dst[HOUT * WOUT] = v.y + bias.y;
        }
    }
}

// ---------------------------------------------------------------------------
// Kernel 2: guide gaussian kernel map.
// ---------------------------------------------------------------------------
#define K2_CK 8

__global__ __launch_bounds__(256) void kmap_kernel(const float* __restrict__ guide) {
    const int b = blockIdx.z;
    const int h0 = blockIdx.y * 16;
    const int w0 = blockIdx.x * 16;
    __shared__ float sg[K2_CK][18][18];
    const int t = threadIdx.x;
    const int tx = t & 15, ty = t >> 4;

    float acc[9];
#pragma unroll
    for (int i = 0; i < 9; i++) acc[i] = 0.f;

    for (int cb = 0; cb < CO; cb += K2_CK) {
        for (int e = t; e < K2_CK * 18 * 18; e += 256) {
            int c = e / 324;
            int rem = e - c * 324;
            int row = rem / 18, col = rem - row * 18;
            int gh = h0 - 1 + row, gw = w0 - 1 + col;
            float v = 0.f;
            if ((unsigned)gh < HOUT && (unsigned)gw < WOUT)
                v = guide[((b * CO + cb + c) * HOUT + gh) * WOUT + gw];
            sg[c][row][col] = v;
        }
        __syncthreads();
#pragma unroll
        for (int c = 0; c < K2_CK; c++) {
            float gc = sg[c][ty + 1][tx + 1];
#pragma unroll
            for (int tap = 0; tap < 9; tap++) {
                int di = tap / 3, dj = tap % 3;
                float d = sg[c][ty + di][tx + dj] - gc;
                acc[tap] += d * d;
            }
        }
        __syncthreads();
    }
#pragma unroll
    for (int tap = 0; tap < 9; tap++)
        g_k[((b * 9 + tap) * HOUT + h0 + ty) * WOUT + w0 + tx] = __expf(-0.5f * acc[tap]);
}

// ---------------------------------------------------------------------------
// Kernel 3: PAC conv, cp.async double buffer.
// ---------------------------------------------------------------------------
#define K3_CK 8
#define K3_XT (K3_CK * 6 * 34)      // 1632 floats per buffer
#define K3_WT (9 * K3_CK * 64)      // 4608 floats per buffer

__global__ __launch_bounds__(256) void pac_kernel(const float* __restrict__ b2,
                                                  float* __restrict__ out) {
    const int bz = blockIdx.z;
    const int b = bz >> 1;
    const int co0 = (bz & 1) * 64;
    const int h0 = blockIdx.y * 4;
    const int w0 = blockIdx.x * 32;

    __shared__ float sys[2][K3_XT];
    __shared__ float sws[2][K3_WT];
    __shared__ float sk[9][4][32];

    const int t = threadIdx.x;
    const int tp = t & 31, tc = t >> 5;

    for (int e = t; e < 9 * 4 * 32; e += 256) {
        int tap = e >> 7;
        int rem = e & 127;
        sk[tap][rem >> 5][rem & 31] =
            g_k[((b * 9 + tap) * HOUT + h0 + (rem >> 5)) * WOUT + w0 + (rem & 31)];
    }

    u64 acc[4][4];
#pragma unroll
    for (int p = 0; p < 4; p++)
#pragma unroll
        for (int q = 0; q < 4; q++) acc[p][q] = 0ull;

    const unsigned sy_s0 = (unsigned)__cvta_generic_to_shared(&sys[0][0]);
    const unsigned sw_s0 = (unsigned)__cvta_generic_to_shared(&sws[0][0]);

    auto prefetch = [&](int cb, int buf) {
        unsigned sy_s = sy_s0 + buf * (K3_XT * 4);
        unsigned sw_s = sw_s0 + buf * (K3_WT * 4);
#pragma unroll
        for (int it = 0; it < 7; it++) {
            int e = t + it * 256;
            if (e < K3_XT) {
                int ci = e / 204;
                int rem = e - ci * 204;
                int row = rem / 34, col = rem - row * 34;
                int yh = h0 - 1 + row, yw = w0 - 1 + col;
                int ok = ((unsigned)yh < HOUT && (unsigned)yw < WOUT) ? 1 : 0;
                const float* g = ok ? &g_y[((b * CO + cb + ci) * HOUT + yh) * WOUT + yw]
                                    : &g_y[0];
                cp4(sy_s + e * 4, g, ok);
            }
        }
#pragma unroll
        for (int it = 0; it < 5; it++) {
            int e = t + it * 256;          // < 1152 16B ops
            if (e < 9 * K3_CK * 16) {
                int tap = e >> 7;
                int rem = e & 127;
                int ci = rem >> 4;
                int c4 = (rem & 15) << 2;
                cp16(sw_s + (((tap * K3_CK + ci) << 6) + c4) * 4,
                     &g_w2t[(tap * CO + cb + ci) * CO + co0 + c4]);
            }
        }
    };

    prefetch(0, 0);
    CP_COMMIT;

    int buf = 0;
    for (int cb = 0; cb < CO; cb += K3_CK) {
        CP_WAIT0;
        __syncthreads();
        if (cb + K3_CK < CO) {
            prefetch(cb + K3_CK, buf ^ 1);
            CP_COMMIT;
        }
        const float* sy = sys[buf];
        const float* sw = sws[buf];

#pragma unroll
        for (int tap = 0; tap < 9; tap++) {
            const int di = tap / 3, dj = tap - 3 * (tap / 3);
            float k0 = sk[tap][0][tp];
            float k1 = sk[tap][1][tp];
            float k2 = sk[tap][2][tp];
            float k3 = sk[tap][3][tp];
            const float* syb = &sy[di * 34 + dj + tp];
#pragma unroll 2
            for (int ci = 0; ci < K3_CK; ci++) {
                const float* wp = &sw[((tap * K3_CK + ci) << 6) + tc * 8];
                u64 w0 = *(const u64*)&wp[0];
                u64 w1v = *(const u64*)&wp[2];
                u64 w2v = *(const u64*)&wp[4];
                u64 w3v = *(const u64*)&wp[6];
                const float* sp = syb + ci * 204;
                u64 x0 = dup2(sp[0] * k0);
                u64 x1 = dup2(sp[34] * k1);
                u64 x2 = dup2(sp[68] * k2);
                u64 x3 = dup2(sp[102] * k3);
                ffma2(acc[0][0], w0, x0); ffma2(acc[1][0], w1v, x0);
                ffma2(acc[2][0], w2v, x0); ffma2(acc[3][0], w3v, x0);
                ffma2(acc[0][1], w0, x1); ffma2(acc[1][1], w1v, x1);
                ffma2(acc[2][1], w2v, x1); ffma2(acc[3][1], w3v, x1);
                ffma2(acc[0][2], w0, x2); ffma2(acc[1][2], w1v, x2);
                ffma2(acc[2][2], w2v, x2); ffma2(acc[3][2], w3v, x2);
                ffma2(acc[0][3], w0, x3); ffma2(acc[1][3], w1v, x3);
                ffma2(acc[2][3], w2v, x3); ffma2(acc[3][3], w3v, x3);
            }
        }
        buf ^= 1;
    }

#pragma unroll
    for (int p = 0; p < 4; p++) {
        int co = co0 + tc * 8 + 2 * p;
        float2 bias = *(const float2*)&b2[co];
#pragma unroll
        for (int q = 0; q < 4; q++) {
            float2 v = unpack2(acc[p][q]);
            float* dst = &out[((b * CO + co) * HOUT + h0 + q) * WOUT + w0 + tp];
            dst[0] = v.x + bias.x;
            dst[HOUT * WOUT] = v.y + bias.y;
        }
    }
}

// ---------------------------------------------------------------------------
// Launch. Inputs: x, guide, w1, b1, w2, b2. Output: float32.
// ---------------------------------------------------------------------------
extern "C" void kernel_launch(void* const* d_in, const int* in_sizes, int n_in,
                              void* d_out, int out_size) {
    const float* x = (const float*)d_in[0];
    const float* guide = (const float*)d_in[1];
    const float* w1 = (const float*)d_in[2];
    const float* b1 = (const float*)d_in[3];
    const float* w2 = (const float*)d_in[4];
    const float* b2 = (const float*)d_in[5];
    float* out = (float*)d_out;

    tw1_kernel<<<2048, 256>>>(w1);
    tw2_kernel<<<576, 256>>>(w2);
    kmap_kernel<<<dim3(8, 8, 4), 256>>>(guide);
    convt_kernel<<<dim3(2, 32, 16), 256>>>(x, b1);
    pac_kernel<<<dim3(4, 32, 8), 256>>>(b2, out);
}

// round 4
// speedup vs baseline: 1.4155x; 1.0024x over previous
#include <cuda_runtime.h>

#define BATCH 4
#define CIN 256
#define CO 128
#define HIN 64
#define WIN 64
#define HOUT 128
#define WOUT 128

__device__ float g_y[BATCH * CO * HOUT * WOUT];
__device__ float g_k[BATCH * 9 * HOUT * WOUT];
__device__ float g_w1t[16 * CIN * CO];
__device__ float g_w2t[9 * CO * CO];

typedef unsigned long long u64;

__device__ __forceinline__ void ffma2(u64 &d, u64 a, u64 b) {
    asm("fma.rn.f32x2 %0, %1, %2, %0;" : "+l"(d) : "l"(a), "l"(b));
}
__device__ __forceinline__ u64 dup2(float x) {
    u64 r; asm("mov.b64 %0, {%1, %1};" : "=l"(r) : "f"(x)); return r;
}
__device__ __forceinline__ float2 unpack2(u64 v) {
    float2 f; asm("mov.b64 {%0, %1}, %2;" : "=f"(f.x), "=f"(f.y) : "l"(v)); return f;
}
__device__ __forceinline__ void cp4(unsigned s, const void* g, int ok) {
    asm volatile("cp.async.ca.shared.global [%0], [%1], 4, %2;" :: "r"(s), "l"(g), "r"(ok * 4));
}
__device__ __forceinline__ void cp16(unsigned s, const void* g) {
    asm volatile("cp.async.cg.shared.global [%0], [%1], 16;" :: "r"(s), "l"(g));
}
#define CP_COMMIT asm volatile("cp.async.commit_group;" ::: "memory")
#define CP_WAIT0 asm volatile("cp.async.wait_group 0;" ::: "memory")

// ---------------------------------------------------------------------------
// One-shot weight transposes.
// ---------------------------------------------------------------------------
__global__ __launch_bounds__(256) void tw1_kernel(const float* __restrict__ w1) {
    int g = blockIdx.x * 256 + threadIdx.x;
    int k = g >> 15;
    int ci = (g >> 7) & 255;
    int co = g & 127;
    g_w1t[g] = w1[((ci << 7) + co) * 16 + k];
}
__global__ __launch_bounds__(256) void tw2_kernel(const float* __restrict__ w2) {
    int g = blockIdx.x * 256 + threadIdx.x;
    int tap = g >> 14;
    int ci = (g >> 7) & 127;
    int co = g & 127;
    g_w2t[g] = w2[((ci << 7) + co) * 9 + 8 - tap];
}

// ---------------------------------------------------------------------------
// Kernel 1: conv_transpose 4x4 s2 p1, parity classes, cp.async double buffer.
// ---------------------------------------------------------------------------
#define K1_CK 16
#define K1_XT (K1_CK * 6 * 34)      // 3264 floats per buffer
#define K1_WT (4 * K1_CK * 64)      // 4096 floats per buffer

__global__ __launch_bounds__(256) void convt_kernel(const float* __restrict__ x,
                                                    const float* __restrict__ b1) {
    const int bz = blockIdx.z;
    const int b = bz >> 2;
    const int cls = bz & 3;
    const int r = cls >> 1, s = cls & 1;
    const int co0 = (blockIdx.y >> 4) * 64;
    const int m0 = (blockIdx.y & 15) * 4;
    const int n0 = blockIdx.x * 32;

    __shared__ float sxs[2][K1_XT];
    __shared__ float sws[2][K1_WT];

    const int t = threadIdx.x;
    const int tp = t & 31;
    const int tc = t >> 5;

    const int rowadd[2] = {1, r ? 2 : 0};
    const int coladd[2] = {1, s ? 2 : 0};
    const int khs[2] = {r ? 2 : 1, r ? 0 : 3};
    const int kws[2] = {s ? 2 : 1, s ? 0 : 3};
    int xoff[4], kidx[4];
#pragma unroll
    for (int tap = 0; tap < 4; tap++) {
        xoff[tap] = rowadd[tap >> 1] * 34 + coladd[tap & 1] + tp;
        kidx[tap] = khs[tap >> 1] * 4 + kws[tap & 1];
    }

    u64 acc[4][4];
#pragma unroll
    for (int p = 0; p < 4; p++)
#pragma unroll
        for (int q = 0; q < 4; q++) acc[p][q] = 0ull;

    const unsigned sx_s0 = (unsigned)__cvta_generic_to_shared(&sxs[0][0]);
    const unsigned sw_s0 = (unsigned)__cvta_generic_to_shared(&sws[0][0]);

    // prefetch lambda-ish macro via explicit code
    auto prefetch = [&](int cb, int buf) {
        unsigned sx_s = sx_s0 + buf * (K1_XT * 4);
        unsigned sw_s = sw_s0 + buf * (K1_WT * 4);
#pragma unroll
        for (int it = 0; it < 13; it++) {
            int e = t + it * 256;
            if (e < K1_XT) {
                int ci = e / 204;
                int rem = e - ci * 204;
                int row = rem / 34, col = rem - row * 34;
                int ih = m0 - 1 + row, iw = n0 - 1 + col;
                int ok = ((unsigned)ih < HIN && (unsigned)iw < WIN) ? 1 : 0;
                const float* g = ok ? &x[((b * CIN + cb + ci) * HIN + ih) * WIN + iw] : x;
                cp4(sx_s + e * 4, g, ok);
            }
        }
#pragma unroll
        for (int it = 0; it < 4; it++) {
            int e = t + it * 256;          // < 1024 16B ops
            int tap = e >> 8;
            int rem = e & 255;
            int ci = rem >> 4;
            int c4 = (rem & 15) << 2;
            cp16(sw_s + (((tap * K1_CK + ci) << 6) + c4) * 4,
                 &g_w1t[(kidx[tap] * CIN + cb + ci) * CO + co0 + c4]);
        }
    };

    prefetch(0, 0);
    CP_COMMIT;

    int buf = 0;
    for (int cb = 0; cb < CIN; cb += K1_CK) {
        CP_WAIT0;
        __syncthreads();
        if (cb + K1_CK < CIN) {
            prefetch(cb + K1_CK, buf ^ 1);
            CP_COMMIT;
        }
        const float* sx = sxs[buf];
        const float* sw = sws[buf];

#pragma unroll 4
        for (int ci = 0; ci < K1_CK; ci++) {
#pragma unroll
            for (int tap = 0; tap < 4; tap++) {
                const float* wp = &sw[((tap * K1_CK + ci) << 6) + tc * 8];
                u64 w0 = *(const u64*)&wp[0];
                u64 w1v = *(const u64*)&wp[2];
                u64 w2v = *(const u64*)&wp[4];
                u64 w3v = *(const u64*)&wp[6];
                const float* sp = &sx[ci * 204 + xoff[tap]];
                u64 x0 = dup2(sp[0]);
                u64 x1 = dup2(sp[34]);
                u64 x2 = dup2(sp[68]);
                u64 x3 = dup2(sp[102]);
                ffma2(acc[0][0], w0, x0); ffma2(acc[1][0], w1v, x0);
                ffma2(acc[2][0], w2v, x0); ffma2(acc[3][0], w3v, x0);
                ffma2(acc[0][1], w0, x1); ffma2(acc[1][1], w1v, x1);
                ffma2(acc[2][1], w2v, x1); ffma2(acc[3][1], w3v, x1);
                ffma2(acc[0][2], w0, x2); ffma2(acc[1][2], w1v, x2);
                ffma2(acc[2][2], w2v, x2); ffma2(acc[3][2], w3v, x2);
                ffma2(acc[0][3], w0, x3); ffma2(acc[1][3], w1v, x3);
                ffma2(acc[2][3], w2v, x3); ffma2(acc[3][3], w3v, x3);
            }
        }
        buf ^= 1;
    }

#pragma unroll
    for (int p = 0; p < 4; p++) {
        int co = co0 + tc * 8 + 2 * p;
        float2 bias = *(const float2*)&b1[co];
#pragma unroll
        for (int q = 0; q < 4; q++) {
            float2 v = unpack2(acc[p][q]);
            int oh = 2 * (m0 + q) + r;
            int ow = 2 * (n0 + tp) + s;
            float* dst = &g_y[((b * CO + co) * HOUT + oh) * WOUT + ow];
            dst[0] = v.x + bias.x;
            dst[HOUT * WOUT] = v.y + bias.y;
        }
    }
}

// ---------------------------------------------------------------------------
// Kernel 2: guide gaussian kernel map.
// ---------------------------------------------------------------------------
#define K2_CK 8

__global__ __launch_bounds__(256) void kmap_kernel(const float* __restrict__ guide) {
    const int b = blockIdx.z;
    const int h0 = blockIdx.y * 16;
    const int w0 = blockIdx.x * 16;
    __shared__ float sg[K2_CK][18][18];
    const int t = threadIdx.x;
    const int tx = t & 15, ty = t >> 4;

    float acc[9];
#pragma unroll
    for (int i = 0; i < 9; i++) acc[i] = 0.f;

    for (int cb = 0; cb < CO; cb += K2_CK) {
        for (int e = t; e < K2_CK * 18 * 18; e += 256) {
            int c = e / 324;
            int rem = e - c * 324;
            int row = rem / 18, col = rem - row * 18;
            int gh = h0 - 1 + row, gw = w0 - 1 + col;
            float v = 0.f;
            if ((unsigned)gh < HOUT && (unsigned)gw < WOUT)
                v = guide[((b * CO + cb + c) * HOUT + gh) * WOUT + gw];
            sg[c][row][col] = v;
        }
        __syncthreads();
#pragma unroll
        for (int c = 0; c < K2_CK; c++) {
            float gc = sg[c][ty + 1][tx + 1];
#pragma unroll
            for (int tap = 0; tap < 9; tap++) {
                int di = tap / 3, dj = tap % 3;
                float d = sg[c][ty + di][tx + dj] - gc;
                acc[tap] += d * d;
            }
        }
        __syncthreads();
    }
#pragma unroll
    for (int tap = 0; tap < 9; tap++)
        g_k[((b * 9 + tap) * HOUT + h0 + ty) * WOUT + w0 + tx] = __expf(-0.5f * acc[tap]);
}

// ---------------------------------------------------------------------------
// Kernel 3: PAC conv, cp.async double buffer.
// ---------------------------------------------------------------------------
#define K3_CK 8
#define K3_XT (K3_CK * 6 * 34)      // 1632 floats per buffer
#define K3_WT (9 * K3_CK * 64)      // 4608 floats per buffer

__global__ __launch_bounds__(256) void pac_kernel(const float* __restrict__ b2,
                                                  float* __restrict__ out) {
    const int bz = blockIdx.z;
    const int b = bz >> 1;
    const int co0 = (bz & 1) * 64;
    const int h0 = blockIdx.y * 4;
    const int w0 = blockIdx.x * 32;

    __shared__ float sys[2][K3_XT];
    __shared__ float sws[2][K3_WT];
    __shared__ float sk[9][4][32];

    const int t = threadIdx.x;
    const int tp = t & 31, tc = t >> 5;

    for (int e = t; e < 9 * 4 * 32; e += 256) {
        int tap = e >> 7;
        int rem = e & 127;
        sk[tap][rem >> 5][rem & 31] =
            g_k[((b * 9 + tap) * HOUT + h0 + (rem >> 5)) * WOUT + w0 + (rem & 31)];
    }

    u64 acc[4][4];
#pragma unroll
    for (int p = 0; p < 4; p++)
#pragma unroll
        for (int q = 0; q < 4; q++) acc[p][q] = 0ull;

    const unsigned sy_s0 = (unsigned)__cvta_generic_to_shared(&sys[0][0]);
    const unsigned sw_s0 = (unsigned)__cvta_generic_to_shared(&sws[0][0]);

    auto prefetch = [&](int cb, int buf) {
        unsigned sy_s = sy_s0 + buf * (K3_XT * 4);
        unsigned sw_s = sw_s0 + buf * (K3_WT * 4);
#pragma unroll
        for (int it = 0; it < 7; it++) {
            int e = t + it * 256;
            if (e < K3_XT) {
                int ci = e / 204;
                int rem = e - ci * 204;
                int row = rem / 34, col = rem - row * 34;
                int yh = h0 - 1 + row, yw = w0 - 1 + col;
                int ok = ((unsigned)yh < HOUT && (unsigned)yw < WOUT) ? 1 : 0;
                const float* g = ok ? &g_y[((b * CO + cb + ci) * HOUT + yh) * WOUT + yw]
                                    : &g_y[0];
                cp4(sy_s + e * 4, g, ok);
            }
        }
#pragma unroll
        for (int it = 0; it < 5; it++) {
            int e = t + it * 256;          // < 1152 16B ops
            if (e < 9 * K3_CK * 16) {
                int tap = e >> 7;
                int rem = e & 127;
                int ci = rem >> 4;
                int c4 = (rem & 15) << 2;
                cp16(sw_s + (((tap * K3_CK + ci) << 6) + c4) * 4,
                     &g_w2t[(tap * CO + cb + ci) * CO + co0 + c4]);
            }
        }
    };

    prefetch(0, 0);
    CP_COMMIT;

    int buf = 0;
    for (int cb = 0; cb < CO; cb += K3_CK) {
        CP_WAIT0;
        __syncthreads();
        if (cb + K3_CK < CO) {
            prefetch(cb + K3_CK, buf ^ 1);
            CP_COMMIT;
        }
        const float* sy = sys[buf];
        const float* sw = sws[buf];

#pragma unroll
        for (int tap = 0; tap < 9; tap++) {
            const int di = tap / 3, dj = tap - 3 * (tap / 3);
            float k0 = sk[tap][0][tp];
            float k1 = sk[tap][1][tp];
            float k2 = sk[tap][2][tp];
            float k3 = sk[tap][3][tp];
            const float* syb = &sy[di * 34 + dj + tp];
#pragma unroll 2
            for (int ci = 0; ci < K3_CK; ci++) {
                const float* wp = &sw[((tap * K3_CK + ci) << 6) + tc * 8];
                u64 w0 = *(const u64*)&wp[0];
                u64 w1v = *(const u64*)&wp[2];
                u64 w2v = *(const u64*)&wp[4];
                u64 w3v = *(const u64*)&wp[6];
                const float* sp = syb + ci * 204;
                u64 x0 = dup2(sp[0] * k0);
                u64 x1 = dup2(sp[34] * k1);
                u64 x2 = dup2(sp[68] * k2);
                u64 x3 = dup2(sp[102] * k3);
                ffma2(acc[0][0], w0, x0); ffma2(acc[1][0], w1v, x0);
                ffma2(acc[2][0], w2v, x0); ffma2(acc[3][0], w3v, x0);
                ffma2(acc[0][1], w0, x1); ffma2(acc[1][1], w1v, x1);
                ffma2(acc[2][1], w2v, x1); ffma2(acc[3][1], w3v, x1);
                ffma2(acc[0][2], w0, x2); ffma2(acc[1][2], w1v, x2);
                ffma2(acc[2][2], w2v, x2); ffma2(acc[3][2], w3v, x2);
                ffma2(acc[0][3], w0, x3); ffma2(acc[1][3], w1v, x3);
                ffma2(acc[2][3], w2v, x3); ffma2(acc[3][3], w3v, x3);
            }
        }
        buf ^= 1;
    }

#pragma unroll
    for (int p = 0; p < 4; p++) {
        int co = co0 + tc * 8 + 2 * p;
        float2 bias = *(const float2*)&b2[co];
#pragma unroll
        for (int q = 0; q < 4; q++) {
            float2 v = unpack2(acc[p][q]);
            float* dst = &out[((b * CO + co) * HOUT + h0 + q) * WOUT + w0 + tp];
            dst[0] = v.x + bias.x;
            dst[HOUT * WOUT] = v.y + bias.y;
        }
    }
}

// ---------------------------------------------------------------------------
// Launch. Inputs: x, guide, w1, b1, w2, b2. Output: float32.
// ---------------------------------------------------------------------------
extern "C" void kernel_launch(void* const* d_in, const int* in_sizes, int n_in,
                              void* d_out, int out_size) {
    const float* x = (const float*)d_in[0];
    const float* guide = (const float*)d_in[1];
    const float* w1 = (const float*)d_in[2];
    const float* b1 = (const float*)d_in[3];
    const float* w2 = (const float*)d_in[4];
    const float* b2 = (const float*)d_in[5];
    float* out = (float*)d_out;

    tw1_kernel<<<2048, 256>>>(w1);
    tw2_kernel<<<576, 256>>>(w2);
    kmap_kernel<<<dim3(8, 8, 4), 256>>>(guide);
    convt_kernel<<<dim3(2, 32, 16), 256>>>(x, b1);
    pac_kernel<<<dim3(4, 32, 8), 256>>>(b2, out);
}